// round 12
// baseline (speedup 1.0000x reference)
#include <cuda_runtime.h>
#include <cstdint>

// ---------------------------------------------------------------------------
// Problem constants
// ---------------------------------------------------------------------------
#define MAXN   50048      // nodes (N = 50000)
#define MAXE   600064     // edges (E = 600000)
#define MAXG   1024       // graphs (G = 256)
#define MAXL   8          // layers (L = 5)
#define DIM    128        // D
#define HID    256        // 2*D
#define VV     128        // vocab

// ---------------------------------------------------------------------------
// Scratch (device globals — no allocation allowed)
// ---------------------------------------------------------------------------
__device__ float g_h    [MAXN * DIM];
__device__ float g_hsum [MAXN * DIM];
__device__ float g_agg  [MAXN * DIM];
__device__ float g_z1   [MAXN * HID];
__device__ float g_hpre [MAXN * DIM];

__device__ int   g_rowptr[MAXN + 1];
__device__ int   g_cnt   [MAXN];
__device__ int4  g_csr   [MAXE];     // packed (src, a0, a1, a2) in CSR order

// per-layer raw BN stats: layer l -> [sum1:256 | sq1:256 | sum2:128 | sq2:128]
#define STATS_STRIDE 768
__device__ float g_stats[MAXL * STATS_STRIDE];

__device__ float g_rep [MAXG * DIM];
__device__ float g_fca [MAXG * 1024];
__device__ float g_fcb [MAXG * 1024];
__device__ float g_fcc [MAXG * 512];

// ---------------------------------------------------------------------------
// tf32 helpers
// ---------------------------------------------------------------------------
__device__ __forceinline__ uint32_t f2tf32(float x)
{
    uint32_t r;
    asm volatile("cvt.rna.tf32.f32 %0, %1;" : "=r"(r) : "f"(x));
    return r;
}

__device__ __forceinline__ void split_tf32(float v, float& big, float& small)
{
    uint32_t bu = f2tf32(v);
    float bf = __uint_as_float(bu);
    big = bf;
    small = __uint_as_float(f2tf32(v - bf));
}

__device__ __forceinline__ void mma8(float* d, const uint32_t* a, const uint32_t* b)
{
    asm volatile(
        "mma.sync.aligned.m16n8k8.row.col.f32.tf32.tf32.f32 "
        "{%0,%1,%2,%3}, {%4,%5,%6,%7}, {%8,%9}, {%0,%1,%2,%3};\n"
        : "+f"(d[0]), "+f"(d[1]), "+f"(d[2]), "+f"(d[3])
        : "r"(a[0]), "r"(a[1]), "r"(a[2]), "r"(a[3]), "r"(b[0]), "r"(b[1]));
}

// ---------------------------------------------------------------------------
// CSR construction (edge topology is layer-invariant)
// ---------------------------------------------------------------------------
__global__ void count_deg_kernel(const int* __restrict__ ei, int* __restrict__ cnt, int E)
{
    int e = blockIdx.x * blockDim.x + threadIdx.x;
    if (e >= E) return;
    atomicAdd(&cnt[__ldg(&ei[E + e])], 1);
}

// strip-per-thread exclusive scan, single block of 1024 threads
__global__ void scan_kernel(const int* __restrict__ cnt, int* __restrict__ rowptr, int N)
{
    __shared__ int tot[1024];
    int tid = threadIdx.x;
    int stride = (N + 1023) / 1024;
    int i0 = tid * stride;
    int i1 = min(i0 + stride, N);
    if (i0 > N) i0 = N;

    int s = 0;
    for (int i = i0; i < i1; i++) s += cnt[i];
    tot[tid] = s;
    __syncthreads();

    #pragma unroll
    for (int off = 1; off < 1024; off <<= 1) {
        int v = (tid >= off) ? tot[tid - off] : 0;
        __syncthreads();
        tot[tid] += v;
        __syncthreads();
    }

    int run = (tid > 0) ? tot[tid - 1] : 0;
    for (int i = i0; i < i1; i++) { rowptr[i] = run; run += cnt[i]; }
    if (tid == 1023) rowptr[N] = tot[1023];
}

__global__ void scatter_csr_kernel(const int* __restrict__ ei,
                                   const int* __restrict__ attr,
                                   const int* __restrict__ rowptr,
                                   int* __restrict__ cnt,
                                   int4* __restrict__ csr, int E)
{
    int e = blockIdx.x * blockDim.x + threadIdx.x;
    if (e >= E) return;
    int dst = __ldg(&ei[E + e]);
    int pos = atomicAdd(&cnt[dst], 1);
    csr[__ldg(&rowptr[dst]) + pos] =
        make_int4(__ldg(&ei[e]), __ldg(&attr[e * 3 + 0]),
                  __ldg(&attr[e * 3 + 1]), __ldg(&attr[e * 3 + 2]));
}

// ---------------------------------------------------------------------------
// Atom encoder
// ---------------------------------------------------------------------------
__global__ void atom_encode_kernel(const int* __restrict__ x,
                                   const float* __restrict__ emb,
                                   float* __restrict__ h,
                                   float* __restrict__ hsum,
                                   int N)
{
    int gid  = blockIdx.x * blockDim.x + threadIdx.x;
    int node = gid >> 5;
    int lane = gid & 31;
    if (node >= N) return;

    float4 acc = make_float4(0.f, 0.f, 0.f, 0.f);
    #pragma unroll
    for (int f = 0; f < 9; f++) {
        int a = __ldg(&x[node * 9 + f]);
        const float4* p = reinterpret_cast<const float4*>(emb) + (size_t)(f * VV + a) * (DIM / 4);
        float4 v = __ldg(&p[lane]);
        acc.x += v.x; acc.y += v.y; acc.z += v.z; acc.w += v.w;
    }
    size_t o = (size_t)node * (DIM / 4) + lane;
    reinterpret_cast<float4*>(h)[o]    = acc;
    reinterpret_cast<float4*>(hsum)[o] = acc;
}

// ---------------------------------------------------------------------------
// Aggregation with bond tables cached in SMEM (196 KB), persistent blocks.
// Writes agg[n] = (1+eps)*h[n] + sum_{e: dst==n} relu(h[src] + e0 + e1 + e2)
// (the GIN combine is folded in, so GEMM1 uses this as its sole A operand)
// ---------------------------------------------------------------------------
__global__ __launch_bounds__(512)
void agg_smem_kernel(const float* __restrict__ h,
                     float* __restrict__ agg,
                     const int* __restrict__ rowptr,
                     const int4* __restrict__ csr,
                     const float* __restrict__ bond,   // + l*3*VV*DIM
                     const float* __restrict__ epsP, int lidx,
                     int N, int totalWarps)
{
    extern __shared__ float sb[];   // 3 * 128 * 128 floats = 196608 B

    // cooperative table load
    const float4* bsrc = reinterpret_cast<const float4*>(bond);
    float4* bdst = reinterpret_cast<float4*>(sb);
    for (int i = threadIdx.x; i < 3 * VV * (DIM / 4); i += 512)
        bdst[i] = __ldg(&bsrc[i]);
    __syncthreads();

    const float ce = 1.0f + __ldg(&epsP[lidx]);
    const int lane = threadIdx.x & 31;
    int gw = (blockIdx.x * 512 + threadIdx.x) >> 5;

    const float4* h4  = reinterpret_cast<const float4*>(h);
    const float4* sb4 = reinterpret_cast<const float4*>(sb);

    for (int node = gw; node < N; node += totalWarps) {
        int j0 = __ldg(&rowptr[node]);
        int j1 = __ldg(&rowptr[node + 1]);

        float4 hv = __ldg(&h4[(size_t)node * (DIM / 4) + lane]);
        float4 acc = make_float4(ce * hv.x, ce * hv.y, ce * hv.z, ce * hv.w);

        for (int j = j0; j < j1; j++) {
            int4 c = __ldg(&csr[j]);
            float4 v  = __ldg(&h4[(size_t)c.x * (DIM / 4) + lane]);
            float4 e0 = sb4[(0 * VV + c.y) * (DIM / 4) + lane];
            float4 e1 = sb4[(1 * VV + c.z) * (DIM / 4) + lane];
            float4 e2 = sb4[(2 * VV + c.w) * (DIM / 4) + lane];
            acc.x += fmaxf(v.x + e0.x + e1.x + e2.x, 0.f);
            acc.y += fmaxf(v.y + e0.y + e1.y + e2.y, 0.f);
            acc.z += fmaxf(v.z + e0.z + e1.z + e2.z, 0.f);
            acc.w += fmaxf(v.w + e0.w + e1.w + e2.w, 0.f);
        }
        reinterpret_cast<float4*>(agg)[(size_t)node * (DIM / 4) + lane] = acc;
    }
}

// ---------------------------------------------------------------------------
// Tensor-core GEMM (3xTF32), 512 threads (16 warps, warp tile 32x32),
// double-buffered smem, 1 sync/stage.
//   AMODE 0: A as-is
//   AMODE 2: A' = relu(bn(A)) with scale/shift computed in-kernel from stats
// Optional fused epilogue: relu, column sum/sum-sq into csum/csq.
// Block tile 128x128, BK=32, mma.m16n8k8.tf32, XOR swizzle.
// Dynamic smem: 2 x 16384 floats + 512 floats = 133120 bytes.
// Requires N%128==0, K%32==0.
// ---------------------------------------------------------------------------
template <int AMODE, bool RELU_OUT, bool STATS>
__global__ __launch_bounds__(512)
void mma_gemm_kernel(const float* __restrict__ A,
                     const float* __restrict__ B,
                     const float* __restrict__ bias,
                     const float* __restrict__ bnsum,
                     const float* __restrict__ bnsq,
                     const float* __restrict__ bng,
                     const float* __restrict__ bnb,
                     float invN,
                     float* __restrict__ C,
                     int M, int N, int K,
                     float* __restrict__ csum,
                     float* __restrict__ csq)
{
    extern __shared__ float smbase[];
    float* sS = smbase + 32768;   // [K<=256] BN scale
    float* sT = smbase + 33024;   // [K<=256] BN shift

    const int tid = threadIdx.x;
    const int bm = blockIdx.y * 128;
    const int bn = blockIdx.x * 128;

    if (AMODE == 2) {
        for (int c = tid; c < K; c += 512) {
            float mu  = __ldg(&bnsum[c]) * invN;
            float var = __ldg(&bnsq[c]) * invN - mu * mu;
            float s   = rsqrtf(var + 1e-5f) * __ldg(&bng[c]);
            sS[c] = s;
            sT[c] = __ldg(&bnb[c]) - mu * s;
        }
        __syncthreads();
    }

    const int q  = tid & 7;          // A k-quad (0..7)
    const int r0 = tid >> 3;         // A row base (0..63)
    const int kb = tid >> 5;         // B k base (0..15)
    const int n4 = (tid & 31) * 4;   // B col

    float4 ra[2], rb[2];

    auto load_stage = [&](int k0) {
        #pragma unroll
        for (int i = 0; i < 2; i++) {
            int grow = bm + r0 + 64 * i;
            ra[i] = (grow < M)
                ? *reinterpret_cast<const float4*>(A + (size_t)grow * K + k0 + q * 4)
                : make_float4(0.f, 0.f, 0.f, 0.f);
        }
        #pragma unroll
        for (int i = 0; i < 2; i++) {
            int k = kb + 16 * i;
            rb[i] = *reinterpret_cast<const float4*>(B + (size_t)(k0 + k) * N + bn + n4);
        }
    };

    auto store_stage = [&](int k0, float* buf) {
        float* sAb = buf;
        float* sAs = buf + 4096;
        float* sBb = buf + 8192;
        float* sBs = buf + 12288;
        #pragma unroll
        for (int i = 0; i < 2; i++) {
            int r = r0 + 64 * i;
            float4 v = ra[i];
            if (AMODE == 2) {
                int kk = k0 + q * 4;
                v.x = fmaxf(v.x * sS[kk + 0] + sT[kk + 0], 0.f);
                v.y = fmaxf(v.y * sS[kk + 1] + sT[kk + 1], 0.f);
                v.z = fmaxf(v.z * sS[kk + 2] + sT[kk + 2], 0.f);
                v.w = fmaxf(v.w * sS[kk + 3] + sT[kk + 3], 0.f);
            }
            float4 bg, sl;
            split_tf32(v.x, bg.x, sl.x);
            split_tf32(v.y, bg.y, sl.y);
            split_tf32(v.z, bg.z, sl.z);
            split_tf32(v.w, bg.w, sl.w);
            int addr = r * 32 + ((q * 4) ^ ((r & 7) * 4));
            *reinterpret_cast<float4*>(sAb + addr) = bg;
            *reinterpret_cast<float4*>(sAs + addr) = sl;
        }
        #pragma unroll
        for (int i = 0; i < 2; i++) {
            int k = kb + 16 * i;
            float4 v = rb[i];
            float4 bg, sl;
            split_tf32(v.x, bg.x, sl.x);
            split_tf32(v.y, bg.y, sl.y);
            split_tf32(v.z, bg.z, sl.z);
            split_tf32(v.w, bg.w, sl.w);
            int addr = k * 128 + (n4 ^ ((k & 3) * 8));
            *reinterpret_cast<float4*>(sBb + addr) = bg;
            *reinterpret_cast<float4*>(sBs + addr) = sl;
        }
    };

    const int lane = tid & 31;
    const int warp = tid >> 5;        // 0..15
    const int wm = warp & 3;          // 0..3 (M)
    const int wn = warp >> 2;         // 0..3 (N)
    const int grp = lane >> 2;        // 0..7
    const int tig = lane & 3;         // 0..3
    const int swA = grp * 4;
    const int swB = tig * 8;

    float acc[2][4][4];
    #pragma unroll
    for (int mt = 0; mt < 2; mt++)
        #pragma unroll
        for (int nt = 0; nt < 4; nt++)
            #pragma unroll
            for (int i = 0; i < 4; i++) acc[mt][nt][i] = 0.f;

    auto compute_stage = [&](const float* buf) {
        const uint32_t* uAb = reinterpret_cast<const uint32_t*>(buf);
        const uint32_t* uAs = uAb + 4096;
        const uint32_t* uBb = uAb + 8192;
        const uint32_t* uBs = uAb + 12288;
        #pragma unroll
        for (int kk = 0; kk < 4; kk++) {
            int kk8 = kk * 8 + tig;
            int c0 = kk8 ^ swA;
            int c1 = c0 ^ 4;
            uint32_t ab[2][4], as_[2][4], bbf[4][2], bsf[4][2];
            #pragma unroll
            for (int mt = 0; mt < 2; mt++) {
                int m = wm * 32 + mt * 16 + grp;
                ab[mt][0]  = uAb[m * 32 + c0];
                ab[mt][1]  = uAb[(m + 8) * 32 + c0];
                ab[mt][2]  = uAb[m * 32 + c1];
                ab[mt][3]  = uAb[(m + 8) * 32 + c1];
                as_[mt][0] = uAs[m * 32 + c0];
                as_[mt][1] = uAs[(m + 8) * 32 + c0];
                as_[mt][2] = uAs[m * 32 + c1];
                as_[mt][3] = uAs[(m + 8) * 32 + c1];
            }
            #pragma unroll
            for (int nt = 0; nt < 4; nt++) {
                int n = wn * 32 + nt * 8 + grp;
                int a0 = kk8 * 128 + (n ^ swB);
                bbf[nt][0] = uBb[a0];
                bbf[nt][1] = uBb[a0 + 512];
                bsf[nt][0] = uBs[a0];
                bsf[nt][1] = uBs[a0 + 512];
            }
            #pragma unroll
            for (int mt = 0; mt < 2; mt++)
                #pragma unroll
                for (int nt = 0; nt < 4; nt++) {
                    mma8(acc[mt][nt], ab[mt],  bbf[nt]);
                    mma8(acc[mt][nt], as_[mt], bbf[nt]);
                    mma8(acc[mt][nt], ab[mt],  bsf[nt]);
                }
        }
    };

    // ---- double-buffered main loop: one sync per stage ----
    const int nst = K >> 5;
    load_stage(0);
    store_stage(0, smbase);
    __syncthreads();
    for (int s = 0; s < nst; s++) {
        if (s + 1 < nst) {
            load_stage((s + 1) << 5);
            store_stage((s + 1) << 5, smbase + ((s + 1) & 1) * 16384);
        }
        compute_stage(smbase + (s & 1) * 16384);
        __syncthreads();
    }

    // ---- epilogue: bias, opt relu, store, fused column stats ----
    float* ssum = smbase;
    float* ssq  = smbase + 128;
    if (STATS) {
        if (tid < 256) smbase[tid] = 0.f;
        __syncthreads();
    }

    float ps[4][2] = {}, pq[4][2] = {};
    #pragma unroll
    for (int mt = 0; mt < 2; mt++) {
        #pragma unroll
        for (int half = 0; half < 2; half++) {
            int row = bm + wm * 32 + mt * 16 + half * 8 + grp;
            bool ok = (row < M);
            #pragma unroll
            for (int nt = 0; nt < 4; nt++) {
                int coll = wn * 32 + nt * 8 + tig * 2;
                float v0 = acc[mt][nt][half * 2 + 0] + __ldg(&bias[bn + coll]);
                float v1 = acc[mt][nt][half * 2 + 1] + __ldg(&bias[bn + coll + 1]);
                if (RELU_OUT) { v0 = fmaxf(v0, 0.f); v1 = fmaxf(v1, 0.f); }
                if (ok) {
                    *reinterpret_cast<float2*>(C + (size_t)row * N + bn + coll) =
                        make_float2(v0, v1);
                    if (STATS) {
                        ps[nt][0] += v0; pq[nt][0] += v0 * v0;
                        ps[nt][1] += v1; pq[nt][1] += v1 * v1;
                    }
                }
            }
        }
    }
    if (STATS) {
        #pragma unroll
        for (int nt = 0; nt < 4; nt++) {
            int coll = wn * 32 + nt * 8 + tig * 2;
            atomicAdd(&ssum[coll],     ps[nt][0]);
            atomicAdd(&ssum[coll + 1], ps[nt][1]);
            atomicAdd(&ssq[coll],      pq[nt][0]);
            atomicAdd(&ssq[coll + 1],  pq[nt][1]);
        }
        __syncthreads();
        if (tid < 128) {
            atomicAdd(&csum[bn + tid], ssum[tid]);
            atomicAdd(&csq [bn + tid], ssq[tid]);
        }
    }
}

// ---------------------------------------------------------------------------
// Node update: h = bn(h_pre) [opt relu]; h_sum += h (BN params in-kernel)
// ---------------------------------------------------------------------------
__global__ void node_update_kernel(const float* __restrict__ hpre,
                                   const float* __restrict__ bnsum,
                                   const float* __restrict__ bnsq,
                                   const float* __restrict__ gamma,
                                   const float* __restrict__ beta,
                                   float invN,
                                   float* __restrict__ h,
                                   float* __restrict__ hsum,
                                   int N, int do_relu)
{
    __shared__ float sS[DIM], sT[DIM];
    if (threadIdx.x < DIM) {
        int c = threadIdx.x;
        float mu  = __ldg(&bnsum[c]) * invN;
        float var = __ldg(&bnsq[c]) * invN - mu * mu;
        float s   = rsqrtf(var + 1e-5f) * __ldg(&gamma[c]);
        sS[c] = s;
        sT[c] = __ldg(&beta[c]) - mu * s;
    }
    __syncthreads();

    int idx = blockIdx.x * blockDim.x + threadIdx.x;
    int total = N * (DIM / 4);
    if (idx >= total) return;
    int c4 = (idx & (DIM / 4 - 1)) * 4;

    float4 v = reinterpret_cast<const float4*>(hpre)[idx];
    v.x = v.x * sS[c4 + 0] + sT[c4 + 0];
    v.y = v.y * sS[c4 + 1] + sT[c4 + 1];
    v.z = v.z * sS[c4 + 2] + sT[c4 + 2];
    v.w = v.w * sS[c4 + 3] + sT[c4 + 3];
    if (do_relu) {
        v.x = fmaxf(v.x, 0.f); v.y = fmaxf(v.y, 0.f);
        v.z = fmaxf(v.z, 0.f); v.w = fmaxf(v.w, 0.f);
    }
    reinterpret_cast<float4*>(h)[idx] = v;
    float4 hs = reinterpret_cast<float4*>(hsum)[idx];
    hs.x += v.x; hs.y += v.y; hs.z += v.z; hs.w += v.w;
    reinterpret_cast<float4*>(hsum)[idx] = hs;
}

// ---------------------------------------------------------------------------
// Global mean pool
// ---------------------------------------------------------------------------
__device__ __forceinline__ int lower_bound_dev(const int* a, int n, int val)
{
    int lo = 0, hi = n;
    while (lo < hi) {
        int mid = (lo + hi) >> 1;
        if (a[mid] < val) lo = mid + 1; else hi = mid;
    }
    return lo;
}

__global__ void pool_kernel(const float* __restrict__ hsum,
                            const int* __restrict__ batch,
                            float* __restrict__ rep,
                            int N)
{
    int g = blockIdx.x;
    int s = lower_bound_dev(batch, N, g);
    int e = lower_bound_dev(batch, N, g + 1);
    float acc = 0.f;
    for (int n = s; n < e; n++)
        acc += hsum[(size_t)n * DIM + threadIdx.x];
    float cnt = (float)(e - s);
    rep[(size_t)g * DIM + threadIdx.x] = acc / fmaxf(cnt, 1.0f);
}

// ---------------------------------------------------------------------------
// Final FC4
// ---------------------------------------------------------------------------
__global__ void fc4_kernel(const float* __restrict__ zc,
                           const float* __restrict__ w,
                           const float* __restrict__ b,
                           float* __restrict__ out,
                           int G)
{
    int gid  = blockIdx.x * blockDim.x + threadIdx.x;
    int g    = gid >> 5;
    int lane = gid & 31;
    if (g >= G) return;
    float acc = 0.f;
    #pragma unroll 4
    for (int k = lane; k < 512; k += 32)
        acc = fmaf(zc[(size_t)g * 512 + k], __ldg(&w[k]), acc);
    #pragma unroll
    for (int off = 16; off > 0; off >>= 1)
        acc += __shfl_xor_sync(0xffffffffu, acc, off);
    if (lane == 0) out[g] = acc + __ldg(&b[0]);
}

// ---------------------------------------------------------------------------
// Launch
// ---------------------------------------------------------------------------
extern "C" void kernel_launch(void* const* d_in, const int* in_sizes, int n_in,
                              void* d_out, int out_size)
{
    const int*   x        = (const int*)  d_in[0];
    const int*   ei       = (const int*)  d_in[1];
    const int*   attr     = (const int*)  d_in[2];
    const int*   batch    = (const int*)  d_in[3];
    const float* atom_emb = (const float*)d_in[4];
    const float* bond_emb = (const float*)d_in[5];
    const float* eps      = (const float*)d_in[6];
    const float* W1   = (const float*)d_in[7];
    const float* b1   = (const float*)d_in[8];
    const float* g1   = (const float*)d_in[9];
    const float* be1  = (const float*)d_in[10];
    const float* W2   = (const float*)d_in[11];
    const float* b2   = (const float*)d_in[12];
    const float* bn_g = (const float*)d_in[13];
    const float* bn_b = (const float*)d_in[14];
    const float* fcW1 = (const float*)d_in[15];
    const float* fcb1 = (const float*)d_in[16];
    const float* fcW2 = (const float*)d_in[17];
    const float* fcb2 = (const float*)d_in[18];
    const float* fcW3 = (const float*)d_in[19];
    const float* fcb3 = (const float*)d_in[20];
    const float* fcW4 = (const float*)d_in[21];
    const float* fcb4 = (const float*)d_in[22];
    float* out = (float*)d_out;

    const int N = in_sizes[0] / 9;
    const int E = in_sizes[1] / 2;
    const int G = out_size;
    const int L = in_sizes[6];

    float *h, *hsum, *agg, *z1, *hpre, *stats;
    float *rep, *fca, *fcb, *fcc;
    int *rowptr, *cnt;
    int4 *csr;
    cudaGetSymbolAddress((void**)&h,    g_h);
    cudaGetSymbolAddress((void**)&hsum, g_hsum);
    cudaGetSymbolAddress((void**)&agg,  g_agg);
    cudaGetSymbolAddress((void**)&z1,   g_z1);
    cudaGetSymbolAddress((void**)&hpre, g_hpre);
    cudaGetSymbolAddress((void**)&stats, g_stats);
    cudaGetSymbolAddress((void**)&rep,  g_rep);
    cudaGetSymbolAddress((void**)&fca,  g_fca);
    cudaGetSymbolAddress((void**)&fcb,  g_fcb);
    cudaGetSymbolAddress((void**)&fcc,  g_fcc);
    cudaGetSymbolAddress((void**)&rowptr, g_rowptr);
    cudaGetSymbolAddress((void**)&cnt,    g_cnt);
    cudaGetSymbolAddress((void**)&csr,    g_csr);

    const float invN = 1.0f / (float)N;
    const int SMEM_MMA = 133120;            // 2*16384 + 512 floats
    const int SMEM_AGG = 3 * VV * DIM * 4;  // 196608 bytes

    cudaFuncSetAttribute(mma_gemm_kernel<0, false, true>,
                         cudaFuncAttributeMaxDynamicSharedMemorySize, SMEM_MMA);
    cudaFuncSetAttribute(mma_gemm_kernel<2, false, true>,
                         cudaFuncAttributeMaxDynamicSharedMemorySize, SMEM_MMA);
    cudaFuncSetAttribute(mma_gemm_kernel<0, true, false>,
                         cudaFuncAttributeMaxDynamicSharedMemorySize, SMEM_MMA);
    cudaFuncSetAttribute(agg_smem_kernel,
                         cudaFuncAttributeMaxDynamicSharedMemorySize, SMEM_AGG);

    // ---- upfront zeroing of all per-layer stat slices (one memset) ----
    cudaMemsetAsync(stats, 0, (size_t)L * STATS_STRIDE * sizeof(float));

    // ---- CSR build ----
    cudaMemsetAsync(cnt, 0, N * sizeof(int));
    count_deg_kernel<<<(E + 255) / 256, 256>>>(ei, cnt, E);
    scan_kernel<<<1, 1024>>>(cnt, rowptr, N);
    cudaMemsetAsync(cnt, 0, N * sizeof(int));
    scatter_csr_kernel<<<(E + 255) / 256, 256>>>(ei, attr, rowptr, cnt, csr, E);

    // AtomEncoder + h_sum init
    atom_encode_kernel<<<(N + 7) / 8, 256>>>(x, atom_emb, h, hsum, N);

    const int mblocks = (N + 127) / 128;
    const int AGG_BLOCKS = 148;
    const int aggWarps = AGG_BLOCKS * 16;

    for (int l = 0; l < L; l++) {
        float* sum1 = stats + (size_t)l * STATS_STRIDE;
        float* sq1  = sum1 + 256;
        float* sum2 = sum1 + 512;
        float* sq2  = sum1 + 640;

        // message + aggregate + GIN combine (bond tables in smem, no atomics)
        agg_smem_kernel<<<AGG_BLOCKS, 512, SMEM_AGG>>>(
            h, agg, rowptr, csr, bond_emb + (size_t)l * 3 * VV * DIM,
            eps, l, N, aggWarps);

        // z1 = agg @ W1 + b1  (stats fused into epilogue)
        mma_gemm_kernel<0, false, true><<<dim3(HID / 128, mblocks), 512, SMEM_MMA>>>(
            agg, W1, b1, nullptr, nullptr, nullptr, nullptr, invN,
            z1, N, HID, DIM, sum1, sq1);

        // h_pre = relu(bn(z1)) @ W2 + b2  (BN params computed in-kernel)
        mma_gemm_kernel<2, false, true><<<dim3(DIM / 128, mblocks), 512, SMEM_MMA>>>(
            z1, W2, b2, sum1, sq1, g1, be1, invN,
            hpre, N, DIM, HID, sum2, sq2);

        // h = bn(h_pre) [relu if not last]; h_sum += h  (BN params in-kernel)
        node_update_kernel<<<(N * (DIM / 4) + 255) / 256, 256>>>(
            hpre, sum2, sq2, bn_g + (size_t)l * DIM, bn_b + (size_t)l * DIM,
            invN, h, hsum, N, (l < L - 1) ? 1 : 0);
    }

    // global mean pool
    pool_kernel<<<G, DIM>>>(hsum, batch, rep, N);

    // FC head (tensor cores)
    const int gblocks = (G + 127) / 128;
    mma_gemm_kernel<0, true, false><<<dim3(1024 / 128, gblocks), 512, SMEM_MMA>>>(
        rep, fcW1, fcb1, nullptr, nullptr, nullptr, nullptr, invN,
        fca, G, 1024, DIM, nullptr, nullptr);
    mma_gemm_kernel<0, true, false><<<dim3(1024 / 128, gblocks), 512, SMEM_MMA>>>(
        fca, fcW2, fcb2, nullptr, nullptr, nullptr, nullptr, invN,
        fcb, G, 1024, 1024, nullptr, nullptr);
    mma_gemm_kernel<0, true, false><<<dim3(512 / 128, gblocks), 512, SMEM_MMA>>>(
        fcb, fcW3, fcb3, nullptr, nullptr, nullptr, nullptr, invN,
        fcc, G, 512, 1024, nullptr, nullptr);
    fc4_kernel<<<(G + 7) / 8, 256>>>(fcc, fcW4, fcb4, out, G);
}

// round 14
// speedup vs baseline: 1.1037x; 1.1037x over previous
#include <cuda_runtime.h>
#include <cstdint>

// ---------------------------------------------------------------------------
// Problem constants
// ---------------------------------------------------------------------------
#define MAXN   50048      // nodes (N = 50000)
#define MAXE   600064     // edges (E = 600000)
#define MAXG   1024       // graphs (G = 256)
#define MAXL   8          // layers (L = 5)
#define DIM    128        // D
#define HID    256        // 2*D
#define VV     128        // vocab

// ---------------------------------------------------------------------------
// Scratch (device globals — no allocation allowed)
// ---------------------------------------------------------------------------
__device__ float g_h    [MAXN * DIM];
__device__ float g_hsum [MAXN * DIM];
__device__ float g_agg  [MAXN * DIM];
__device__ float g_z1   [MAXN * HID];
__device__ float g_hpre [MAXN * DIM];

__device__ int   g_rowptr[MAXN + 1];
__device__ int   g_cnt   [MAXN];
__device__ int4  g_csr   [MAXE];     // packed (src, a0, a1, a2) in CSR order

// per-layer raw BN stats: layer l -> [sum1:256 | sq1:256 | sum2:128 | sq2:128]
#define STATS_STRIDE 768
__device__ float g_stats[MAXL * STATS_STRIDE];

__device__ float g_rep [MAXG * DIM];
__device__ float g_fca [MAXG * 1024];
__device__ float g_fcb [MAXG * 1024];
__device__ float g_fcc [MAXG * 512];

// ---------------------------------------------------------------------------
// tf32 helpers
// ---------------------------------------------------------------------------
__device__ __forceinline__ uint32_t f2tf32(float x)
{
    uint32_t r;
    asm volatile("cvt.rna.tf32.f32 %0, %1;" : "=r"(r) : "f"(x));
    return r;
}

__device__ __forceinline__ void split_tf32(float v, float& big, float& small)
{
    uint32_t bu = f2tf32(v);
    float bf = __uint_as_float(bu);
    big = bf;
    small = __uint_as_float(f2tf32(v - bf));
}

__device__ __forceinline__ void mma8(float* d, const uint32_t* a, const uint32_t* b)
{
    asm volatile(
        "mma.sync.aligned.m16n8k8.row.col.f32.tf32.tf32.f32 "
        "{%0,%1,%2,%3}, {%4,%5,%6,%7}, {%8,%9}, {%0,%1,%2,%3};\n"
        : "+f"(d[0]), "+f"(d[1]), "+f"(d[2]), "+f"(d[3])
        : "r"(a[0]), "r"(a[1]), "r"(a[2]), "r"(a[3]), "r"(b[0]), "r"(b[1]));
}

// ---------------------------------------------------------------------------
// CSR construction (edge topology is layer-invariant)
// ---------------------------------------------------------------------------
__global__ void count_deg_kernel(const int* __restrict__ ei, int* __restrict__ cnt, int E)
{
    int e = blockIdx.x * blockDim.x + threadIdx.x;
    if (e >= E) return;
    atomicAdd(&cnt[__ldg(&ei[E + e])], 1);
}

// strip-per-thread exclusive scan, single block of 1024 threads
__global__ void scan_kernel(const int* __restrict__ cnt, int* __restrict__ rowptr, int N)
{
    __shared__ int tot[1024];
    int tid = threadIdx.x;
    int stride = (N + 1023) / 1024;
    int i0 = tid * stride;
    int i1 = min(i0 + stride, N);
    if (i0 > N) i0 = N;

    int s = 0;
    for (int i = i0; i < i1; i++) s += cnt[i];
    tot[tid] = s;
    __syncthreads();

    #pragma unroll
    for (int off = 1; off < 1024; off <<= 1) {
        int v = (tid >= off) ? tot[tid - off] : 0;
        __syncthreads();
        tot[tid] += v;
        __syncthreads();
    }

    int run = (tid > 0) ? tot[tid - 1] : 0;
    for (int i = i0; i < i1; i++) { rowptr[i] = run; run += cnt[i]; }
    if (tid == 1023) rowptr[N] = tot[1023];
}

__global__ void scatter_csr_kernel(const int* __restrict__ ei,
                                   const int* __restrict__ attr,
                                   const int* __restrict__ rowptr,
                                   int* __restrict__ cnt,
                                   int4* __restrict__ csr, int E)
{
    int e = blockIdx.x * blockDim.x + threadIdx.x;
    if (e >= E) return;
    int dst = __ldg(&ei[E + e]);
    int pos = atomicAdd(&cnt[dst], 1);
    csr[__ldg(&rowptr[dst]) + pos] =
        make_int4(__ldg(&ei[e]), __ldg(&attr[e * 3 + 0]),
                  __ldg(&attr[e * 3 + 1]), __ldg(&attr[e * 3 + 2]));
}

// ---------------------------------------------------------------------------
// Atom encoder
// ---------------------------------------------------------------------------
__global__ void atom_encode_kernel(const int* __restrict__ x,
                                   const float* __restrict__ emb,
                                   float* __restrict__ h,
                                   float* __restrict__ hsum,
                                   int N)
{
    int gid  = blockIdx.x * blockDim.x + threadIdx.x;
    int node = gid >> 5;
    int lane = gid & 31;
    if (node >= N) return;

    float4 acc = make_float4(0.f, 0.f, 0.f, 0.f);
    #pragma unroll
    for (int f = 0; f < 9; f++) {
        int a = __ldg(&x[node * 9 + f]);
        const float4* p = reinterpret_cast<const float4*>(emb) + (size_t)(f * VV + a) * (DIM / 4);
        float4 v = __ldg(&p[lane]);
        acc.x += v.x; acc.y += v.y; acc.z += v.z; acc.w += v.w;
    }
    size_t o = (size_t)node * (DIM / 4) + lane;
    reinterpret_cast<float4*>(h)[o]    = acc;
    reinterpret_cast<float4*>(hsum)[o] = acc;
}

// ---------------------------------------------------------------------------
// Gather aggregation (packed CSR, GIN combine folded in):
// agg[n] = (1+eps)*h[n] + sum_{e: dst==n} relu(h[src] + e0 + e1 + e2)
// One warp per node, lane owns one float4. 2-way unrolled edge loop for MLP.
// ---------------------------------------------------------------------------
__global__ void agg_gather_kernel(const float* __restrict__ h,
                                  float* __restrict__ agg,
                                  const int* __restrict__ rowptr,
                                  const int4* __restrict__ csr,
                                  const float* __restrict__ bond,  // + l*3*VV*DIM
                                  const float* __restrict__ epsP, int lidx,
                                  int N)
{
    int gid  = blockIdx.x * blockDim.x + threadIdx.x;
    int node = gid >> 5;
    int lane = gid & 31;
    if (node >= N) return;

    int j0 = __ldg(&rowptr[node]);
    int j1 = __ldg(&rowptr[node + 1]);

    const float4* h4 = reinterpret_cast<const float4*>(h);
    const float4* b4 = reinterpret_cast<const float4*>(bond);

    const float ce = 1.0f + __ldg(&epsP[lidx]);
    float4 hv = __ldg(&h4[(size_t)node * (DIM / 4) + lane]);
    float4 acc = make_float4(ce * hv.x, ce * hv.y, ce * hv.z, ce * hv.w);

    int j = j0;
    for (; j + 2 <= j1; j += 2) {
        int4 c0 = __ldg(&csr[j]);
        int4 c1 = __ldg(&csr[j + 1]);

        float4 v0  = __ldg(&h4[(size_t)c0.x * (DIM / 4) + lane]);
        float4 v1  = __ldg(&h4[(size_t)c1.x * (DIM / 4) + lane]);
        float4 ea0 = __ldg(&b4[(0 * VV + c0.y) * (DIM / 4) + lane]);
        float4 ea1 = __ldg(&b4[(0 * VV + c1.y) * (DIM / 4) + lane]);
        float4 eb0 = __ldg(&b4[(1 * VV + c0.z) * (DIM / 4) + lane]);
        float4 eb1 = __ldg(&b4[(1 * VV + c1.z) * (DIM / 4) + lane]);
        float4 ec0 = __ldg(&b4[(2 * VV + c0.w) * (DIM / 4) + lane]);
        float4 ec1 = __ldg(&b4[(2 * VV + c1.w) * (DIM / 4) + lane]);

        acc.x += fmaxf(v0.x + ea0.x + eb0.x + ec0.x, 0.f)
               + fmaxf(v1.x + ea1.x + eb1.x + ec1.x, 0.f);
        acc.y += fmaxf(v0.y + ea0.y + eb0.y + ec0.y, 0.f)
               + fmaxf(v1.y + ea1.y + eb1.y + ec1.y, 0.f);
        acc.z += fmaxf(v0.z + ea0.z + eb0.z + ec0.z, 0.f)
               + fmaxf(v1.z + ea1.z + eb1.z + ec1.z, 0.f);
        acc.w += fmaxf(v0.w + ea0.w + eb0.w + ec0.w, 0.f)
               + fmaxf(v1.w + ea1.w + eb1.w + ec1.w, 0.f);
    }
    if (j < j1) {
        int4 c = __ldg(&csr[j]);
        float4 v  = __ldg(&h4[(size_t)c.x * (DIM / 4) + lane]);
        float4 e0 = __ldg(&b4[(0 * VV + c.y) * (DIM / 4) + lane]);
        float4 e1 = __ldg(&b4[(1 * VV + c.z) * (DIM / 4) + lane]);
        float4 e2 = __ldg(&b4[(2 * VV + c.w) * (DIM / 4) + lane]);
        acc.x += fmaxf(v.x + e0.x + e1.x + e2.x, 0.f);
        acc.y += fmaxf(v.y + e0.y + e1.y + e2.y, 0.f);
        acc.z += fmaxf(v.z + e0.z + e1.z + e2.z, 0.f);
        acc.w += fmaxf(v.w + e0.w + e1.w + e2.w, 0.f);
    }
    reinterpret_cast<float4*>(agg)[(size_t)node * (DIM / 4) + lane] = acc;
}

// ---------------------------------------------------------------------------
// Tensor-core GEMM (3xTF32), 256 threads (8 warps, warp tile 64x32),
// double-buffered smem, 1 sync/stage.
//   AMODE 0: A as-is
//   AMODE 2: A' = relu(bn(A)) with scale/shift computed in-kernel from stats
// Optional fused epilogue: relu, column sum/sum-sq into csum/csq.
// Block tile 128x128, BK=32, mma.m16n8k8.tf32, XOR swizzle.
// Dynamic smem: 2 x 16384 floats + 512 floats = 133120 bytes.
// Requires N%128==0, K%32==0.
// ---------------------------------------------------------------------------
template <int AMODE, bool RELU_OUT, bool STATS>
__global__ __launch_bounds__(256)
void mma_gemm_kernel(const float* __restrict__ A,
                     const float* __restrict__ B,
                     const float* __restrict__ bias,
                     const float* __restrict__ bnsum,
                     const float* __restrict__ bnsq,
                     const float* __restrict__ bng,
                     const float* __restrict__ bnb,
                     float invN,
                     float* __restrict__ C,
                     int M, int N, int K,
                     float* __restrict__ csum,
                     float* __restrict__ csq)
{
    extern __shared__ float smbase[];
    float* sS = smbase + 32768;   // [K<=256] BN scale
    float* sT = smbase + 33024;   // [K<=256] BN shift

    const int tid = threadIdx.x;
    const int bm = blockIdx.y * 128;
    const int bn = blockIdx.x * 128;

    if (AMODE == 2) {
        for (int c = tid; c < K; c += 256) {
            float mu  = __ldg(&bnsum[c]) * invN;
            float var = __ldg(&bnsq[c]) * invN - mu * mu;
            float s   = rsqrtf(var + 1e-5f) * __ldg(&bng[c]);
            sS[c] = s;
            sT[c] = __ldg(&bnb[c]) - mu * s;
        }
        __syncthreads();
    }

    const int q  = tid & 7;          // A k-quad (0..7)
    const int r0 = tid >> 3;         // A row base (0..31)
    const int kb = tid >> 5;         // B k base (0..7)
    const int n4 = (tid & 31) * 4;   // B col

    float4 ra[4], rb[4];

    auto load_stage = [&](int k0) {
        #pragma unroll
        for (int i = 0; i < 4; i++) {
            int grow = bm + r0 + 32 * i;
            ra[i] = (grow < M)
                ? *reinterpret_cast<const float4*>(A + (size_t)grow * K + k0 + q * 4)
                : make_float4(0.f, 0.f, 0.f, 0.f);
        }
        #pragma unroll
        for (int i = 0; i < 4; i++) {
            int k = kb + 8 * i;
            rb[i] = *reinterpret_cast<const float4*>(B + (size_t)(k0 + k) * N + bn + n4);
        }
    };

    auto store_stage = [&](int k0, float* buf) {
        float* sAb = buf;
        float* sAs = buf + 4096;
        float* sBb = buf + 8192;
        float* sBs = buf + 12288;
        #pragma unroll
        for (int i = 0; i < 4; i++) {
            int r = r0 + 32 * i;
            float4 v = ra[i];
            if (AMODE == 2) {
                int kk = k0 + q * 4;
                v.x = fmaxf(v.x * sS[kk + 0] + sT[kk + 0], 0.f);
                v.y = fmaxf(v.y * sS[kk + 1] + sT[kk + 1], 0.f);
                v.z = fmaxf(v.z * sS[kk + 2] + sT[kk + 2], 0.f);
                v.w = fmaxf(v.w * sS[kk + 3] + sT[kk + 3], 0.f);
            }
            float4 bg, sl;
            split_tf32(v.x, bg.x, sl.x);
            split_tf32(v.y, bg.y, sl.y);
            split_tf32(v.z, bg.z, sl.z);
            split_tf32(v.w, bg.w, sl.w);
            int addr = r * 32 + ((q * 4) ^ ((r & 7) * 4));
            *reinterpret_cast<float4*>(sAb + addr) = bg;
            *reinterpret_cast<float4*>(sAs + addr) = sl;
        }
        #pragma unroll
        for (int i = 0; i < 4; i++) {
            int k = kb + 8 * i;
            float4 v = rb[i];
            float4 bg, sl;
            split_tf32(v.x, bg.x, sl.x);
            split_tf32(v.y, bg.y, sl.y);
            split_tf32(v.z, bg.z, sl.z);
            split_tf32(v.w, bg.w, sl.w);
            int addr = k * 128 + (n4 ^ ((k & 3) * 8));
            *reinterpret_cast<float4*>(sBb + addr) = bg;
            *reinterpret_cast<float4*>(sBs + addr) = sl;
        }
    };

    const int lane = tid & 31;
    const int warp = tid >> 5;
    const int wm = warp & 1;
    const int wn = warp >> 1;
    const int grp = lane >> 2;
    const int tig = lane & 3;
    const int swA = grp * 4;
    const int swB = tig * 8;

    float acc[4][4][4];
    #pragma unroll
    for (int mt = 0; mt < 4; mt++)
        #pragma unroll
        for (int nt = 0; nt < 4; nt++)
            #pragma unroll
            for (int i = 0; i < 4; i++) acc[mt][nt][i] = 0.f;

    auto compute_stage = [&](const float* buf) {
        const uint32_t* uAb = reinterpret_cast<const uint32_t*>(buf);
        const uint32_t* uAs = uAb + 4096;
        const uint32_t* uBb = uAb + 8192;
        const uint32_t* uBs = uAb + 12288;
        #pragma unroll
        for (int kk = 0; kk < 4; kk++) {
            int kk8 = kk * 8 + tig;
            int c0 = kk8 ^ swA;
            int c1 = c0 ^ 4;
            uint32_t ab[4][4], as_[4][4], bbf[4][2], bsf[4][2];
            #pragma unroll
            for (int mt = 0; mt < 4; mt++) {
                int m = wm * 64 + mt * 16 + grp;
                ab[mt][0]  = uAb[m * 32 + c0];
                ab[mt][1]  = uAb[(m + 8) * 32 + c0];
                ab[mt][2]  = uAb[m * 32 + c1];
                ab[mt][3]  = uAb[(m + 8) * 32 + c1];
                as_[mt][0] = uAs[m * 32 + c0];
                as_[mt][1] = uAs[(m + 8) * 32 + c0];
                as_[mt][2] = uAs[m * 32 + c1];
                as_[mt][3] = uAs[(m + 8) * 32 + c1];
            }
            #pragma unroll
            for (int nt = 0; nt < 4; nt++) {
                int n = wn * 32 + nt * 8 + grp;
                int a0 = kk8 * 128 + (n ^ swB);
                bbf[nt][0] = uBb[a0];
                bbf[nt][1] = uBb[a0 + 512];
                bsf[nt][0] = uBs[a0];
                bsf[nt][1] = uBs[a0 + 512];
            }
            #pragma unroll
            for (int mt = 0; mt < 4; mt++)
                #pragma unroll
                for (int nt = 0; nt < 4; nt++) {
                    mma8(acc[mt][nt], ab[mt],  bbf[nt]);
                    mma8(acc[mt][nt], as_[mt], bbf[nt]);
                    mma8(acc[mt][nt], ab[mt],  bsf[nt]);
                }
        }
    };

    // ---- double-buffered main loop: one sync per stage ----
    const int nst = K >> 5;
    load_stage(0);
    store_stage(0, smbase);
    __syncthreads();
    for (int s = 0; s < nst; s++) {
        if (s + 1 < nst) {
            load_stage((s + 1) << 5);
            store_stage((s + 1) << 5, smbase + ((s + 1) & 1) * 16384);
        }
        compute_stage(smbase + (s & 1) * 16384);
        __syncthreads();
    }

    // ---- epilogue: bias, opt relu, store, fused column stats ----
    float* ssum = smbase;
    float* ssq  = smbase + 128;
    if (STATS) {
        smbase[tid] = 0.f;
        __syncthreads();
    }

    float ps[4][2] = {}, pq[4][2] = {};
    #pragma unroll
    for (int mt = 0; mt < 4; mt++) {
        #pragma unroll
        for (int half = 0; half < 2; half++) {
            int row = bm + wm * 64 + mt * 16 + half * 8 + grp;
            bool ok = (row < M);
            #pragma unroll
            for (int nt = 0; nt < 4; nt++) {
                int coll = wn * 32 + nt * 8 + tig * 2;
                float v0 = acc[mt][nt][half * 2 + 0] + __ldg(&bias[bn + coll]);
                float v1 = acc[mt][nt][half * 2 + 1] + __ldg(&bias[bn + coll + 1]);
                if (RELU_OUT) { v0 = fmaxf(v0, 0.f); v1 = fmaxf(v1, 0.f); }
                if (ok) {
                    *reinterpret_cast<float2*>(C + (size_t)row * N + bn + coll) =
                        make_float2(v0, v1);
                    if (STATS) {
                        ps[nt][0] += v0; pq[nt][0] += v0 * v0;
                        ps[nt][1] += v1; pq[nt][1] += v1 * v1;
                    }
                }
            }
        }
    }
    if (STATS) {
        #pragma unroll
        for (int nt = 0; nt < 4; nt++) {
            int coll = wn * 32 + nt * 8 + tig * 2;
            atomicAdd(&ssum[coll],     ps[nt][0]);
            atomicAdd(&ssum[coll + 1], ps[nt][1]);
            atomicAdd(&ssq[coll],      pq[nt][0]);
            atomicAdd(&ssq[coll + 1],  pq[nt][1]);
        }
        __syncthreads();
        if (tid < 128) {
            atomicAdd(&csum[bn + tid], ssum[tid]);
            atomicAdd(&csq [bn + tid], ssq[tid]);
        }
    }
}

// ---------------------------------------------------------------------------
// Node update: h = bn(h_pre) [opt relu]; h_sum += h (BN params in-kernel)
// ---------------------------------------------------------------------------
__global__ void node_update_kernel(const float* __restrict__ hpre,
                                   const float* __restrict__ bnsum,
                                   const float* __restrict__ bnsq,
                                   const float* __restrict__ gamma,
                                   const float* __restrict__ beta,
                                   float invN,
                                   float* __restrict__ h,
                                   float* __restrict__ hsum,
                                   int N, int do_relu)
{
    __shared__ float sS[DIM], sT[DIM];
    if (threadIdx.x < DIM) {
        int c = threadIdx.x;
        float mu  = __ldg(&bnsum[c]) * invN;
        float var = __ldg(&bnsq[c]) * invN - mu * mu;
        float s   = rsqrtf(var + 1e-5f) * __ldg(&gamma[c]);
        sS[c] = s;
        sT[c] = __ldg(&beta[c]) - mu * s;
    }
    __syncthreads();

    int idx = blockIdx.x * blockDim.x + threadIdx.x;
    int total = N * (DIM / 4);
    if (idx >= total) return;
    int c4 = (idx & (DIM / 4 - 1)) * 4;

    float4 v = reinterpret_cast<const float4*>(hpre)[idx];
    v.x = v.x * sS[c4 + 0] + sT[c4 + 0];
    v.y = v.y * sS[c4 + 1] + sT[c4 + 1];
    v.z = v.z * sS[c4 + 2] + sT[c4 + 2];
    v.w = v.w * sS[c4 + 3] + sT[c4 + 3];
    if (do_relu) {
        v.x = fmaxf(v.x, 0.f); v.y = fmaxf(v.y, 0.f);
        v.z = fmaxf(v.z, 0.f); v.w = fmaxf(v.w, 0.f);
    }
    reinterpret_cast<float4*>(h)[idx] = v;
    float4 hs = reinterpret_cast<float4*>(hsum)[idx];
    hs.x += v.x; hs.y += v.y; hs.z += v.z; hs.w += v.w;
    reinterpret_cast<float4*>(hsum)[idx] = hs;
}

// ---------------------------------------------------------------------------
// Global mean pool
// ---------------------------------------------------------------------------
__device__ __forceinline__ int lower_bound_dev(const int* a, int n, int val)
{
    int lo = 0, hi = n;
    while (lo < hi) {
        int mid = (lo + hi) >> 1;
        if (a[mid] < val) lo = mid + 1; else hi = mid;
    }
    return lo;
}

__global__ void pool_kernel(const float* __restrict__ hsum,
                            const int* __restrict__ batch,
                            float* __restrict__ rep,
                            int N)
{
    int g = blockIdx.x;
    int s = lower_bound_dev(batch, N, g);
    int e = lower_bound_dev(batch, N, g + 1);
    float acc = 0.f;
    for (int n = s; n < e; n++)
        acc += hsum[(size_t)n * DIM + threadIdx.x];
    float cnt = (float)(e - s);
    rep[(size_t)g * DIM + threadIdx.x] = acc / fmaxf(cnt, 1.0f);
}

// ---------------------------------------------------------------------------
// Final FC4
// ---------------------------------------------------------------------------
__global__ void fc4_kernel(const float* __restrict__ zc,
                           const float* __restrict__ w,
                           const float* __restrict__ b,
                           float* __restrict__ out,
                           int G)
{
    int gid  = blockIdx.x * blockDim.x + threadIdx.x;
    int g    = gid >> 5;
    int lane = gid & 31;
    if (g >= G) return;
    float acc = 0.f;
    #pragma unroll 4
    for (int k = lane; k < 512; k += 32)
        acc = fmaf(zc[(size_t)g * 512 + k], __ldg(&w[k]), acc);
    #pragma unroll
    for (int off = 16; off > 0; off >>= 1)
        acc += __shfl_xor_sync(0xffffffffu, acc, off);
    if (lane == 0) out[g] = acc + __ldg(&b[0]);
}

// ---------------------------------------------------------------------------
// Launch
// ---------------------------------------------------------------------------
extern "C" void kernel_launch(void* const* d_in, const int* in_sizes, int n_in,
                              void* d_out, int out_size)
{
    const int*   x        = (const int*)  d_in[0];
    const int*   ei       = (const int*)  d_in[1];
    const int*   attr     = (const int*)  d_in[2];
    const int*   batch    = (const int*)  d_in[3];
    const float* atom_emb = (const float*)d_in[4];
    const float* bond_emb = (const float*)d_in[5];
    const float* eps      = (const float*)d_in[6];
    const float* W1   = (const float*)d_in[7];
    const float* b1   = (const float*)d_in[8];
    const float* g1   = (const float*)d_in[9];
    const float* be1  = (const float*)d_in[10];
    const float* W2   = (const float*)d_in[11];
    const float* b2   = (const float*)d_in[12];
    const float* bn_g = (const float*)d_in[13];
    const float* bn_b = (const float*)d_in[14];
    const float* fcW1 = (const float*)d_in[15];
    const float* fcb1 = (const float*)d_in[16];
    const float* fcW2 = (const float*)d_in[17];
    const float* fcb2 = (const float*)d_in[18];
    const float* fcW3 = (const float*)d_in[19];
    const float* fcb3 = (const float*)d_in[20];
    const float* fcW4 = (const float*)d_in[21];
    const float* fcb4 = (const float*)d_in[22];
    float* out = (float*)d_out;

    const int N = in_sizes[0] / 9;
    const int E = in_sizes[1] / 2;
    const int G = out_size;
    const int L = in_sizes[6];

    float *h, *hsum, *agg, *z1, *hpre, *stats;
    float *rep, *fca, *fcb, *fcc;
    int *rowptr, *cnt;
    int4 *csr;
    cudaGetSymbolAddress((void**)&h,    g_h);
    cudaGetSymbolAddress((void**)&hsum, g_hsum);
    cudaGetSymbolAddress((void**)&agg,  g_agg);
    cudaGetSymbolAddress((void**)&z1,   g_z1);
    cudaGetSymbolAddress((void**)&hpre, g_hpre);
    cudaGetSymbolAddress((void**)&stats, g_stats);
    cudaGetSymbolAddress((void**)&rep,  g_rep);
    cudaGetSymbolAddress((void**)&fca,  g_fca);
    cudaGetSymbolAddress((void**)&fcb,  g_fcb);
    cudaGetSymbolAddress((void**)&fcc,  g_fcc);
    cudaGetSymbolAddress((void**)&rowptr, g_rowptr);
    cudaGetSymbolAddress((void**)&cnt,    g_cnt);
    cudaGetSymbolAddress((void**)&csr,    g_csr);

    const float invN = 1.0f / (float)N;
    const int SMEM_MMA = 133120;   // 2*16384 + 512 floats

    cudaFuncSetAttribute(mma_gemm_kernel<0, false, true>,
                         cudaFuncAttributeMaxDynamicSharedMemorySize, SMEM_MMA);
    cudaFuncSetAttribute(mma_gemm_kernel<2, false, true>,
                         cudaFuncAttributeMaxDynamicSharedMemorySize, SMEM_MMA);
    cudaFuncSetAttribute(mma_gemm_kernel<0, true, false>,
                         cudaFuncAttributeMaxDynamicSharedMemorySize, SMEM_MMA);

    // ---- upfront zeroing of all per-layer stat slices (one memset) ----
    cudaMemsetAsync(stats, 0, (size_t)L * STATS_STRIDE * sizeof(float));

    // ---- CSR build ----
    cudaMemsetAsync(cnt, 0, N * sizeof(int));
    count_deg_kernel<<<(E + 255) / 256, 256>>>(ei, cnt, E);
    scan_kernel<<<1, 1024>>>(cnt, rowptr, N);
    cudaMemsetAsync(cnt, 0, N * sizeof(int));
    scatter_csr_kernel<<<(E + 255) / 256, 256>>>(ei, attr, rowptr, cnt, csr, E);

    // AtomEncoder + h_sum init
    atom_encode_kernel<<<(N + 7) / 8, 256>>>(x, atom_emb, h, hsum, N);

    const int mblocks = (N + 127) / 128;

    for (int l = 0; l < L; l++) {
        float* sum1 = stats + (size_t)l * STATS_STRIDE;
        float* sq1  = sum1 + 256;
        float* sum2 = sum1 + 512;
        float* sq2  = sum1 + 640;

        // message + aggregate + GIN combine (gather, packed CSR, no atomics)
        agg_gather_kernel<<<(N * 32 + 255) / 256, 256>>>(
            h, agg, rowptr, csr, bond_emb + (size_t)l * 3 * VV * DIM,
            eps, l, N);

        // z1 = agg @ W1 + b1  (stats fused into epilogue)
        mma_gemm_kernel<0, false, true><<<dim3(HID / 128, mblocks), 256, SMEM_MMA>>>(
            agg, W1, b1, nullptr, nullptr, nullptr, nullptr, invN,
            z1, N, HID, DIM, sum1, sq1);

        // h_pre = relu(bn(z1)) @ W2 + b2  (BN params computed in-kernel)
        mma_gemm_kernel<2, false, true><<<dim3(DIM / 128, mblocks), 256, SMEM_MMA>>>(
            z1, W2, b2, sum1, sq1, g1, be1, invN,
            hpre, N, DIM, HID, sum2, sq2);

        // h = bn(h_pre) [relu if not last]; h_sum += h  (BN params in-kernel)
        node_update_kernel<<<(N * (DIM / 4) + 255) / 256, 256>>>(
            hpre, sum2, sq2, bn_g + (size_t)l * DIM, bn_b + (size_t)l * DIM,
            invN, h, hsum, N, (l < L - 1) ? 1 : 0);
    }

    // global mean pool
    pool_kernel<<<G, DIM>>>(hsum, batch, rep, N);

    // FC head (tensor cores)
    const int gblocks = (G + 127) / 128;
    mma_gemm_kernel<0, true, false><<<dim3(1024 / 128, gblocks), 256, SMEM_MMA>>>(
        rep, fcW1, fcb1, nullptr, nullptr, nullptr, nullptr, invN,
        fca, G, 1024, DIM, nullptr, nullptr);
    mma_gemm_kernel<0, true, false><<<dim3(1024 / 128, gblocks), 256, SMEM_MMA>>>(
        fca, fcW2, fcb2, nullptr, nullptr, nullptr, nullptr, invN,
        fcb, G, 1024, 1024, nullptr, nullptr);
    mma_gemm_kernel<0, true, false><<<dim3(512 / 128, gblocks), 256, SMEM_MMA>>>(
        fcb, fcW3, fcb3, nullptr, nullptr, nullptr, nullptr, invN,
        fcc, G, 512, 1024, nullptr, nullptr);
    fc4_kernel<<<(G + 7) / 8, 256>>>(fcc, fcW4, fcb4, out, G);
}

// round 15
// speedup vs baseline: 1.1065x; 1.0025x over previous
#include <cuda_runtime.h>
#include <cstdint>

// ---------------------------------------------------------------------------
// Problem constants
// ---------------------------------------------------------------------------
#define MAXN   50048      // nodes (N = 50000)
#define MAXE   600064     // edges (E = 600000)
#define MAXG   1024       // graphs (G = 256)
#define MAXL   8          // layers (L = 5)
#define DIM    128        // D
#define HID    256        // 2*D
#define VV     128        // vocab

// ---------------------------------------------------------------------------
// Scratch (device globals — no allocation allowed)
// ---------------------------------------------------------------------------
__device__ float g_h    [MAXN * DIM];
__device__ float g_hsum [MAXN * DIM];
__device__ float g_agg  [MAXN * DIM];
__device__ float g_z1   [MAXN * HID];
__device__ float g_hpre [MAXN * DIM];

__device__ int   g_rowptr[MAXN + 1];
__device__ int   g_cnt   [MAXN];
__device__ int4  g_csr   [MAXE];     // packed (src, a0, a1, a2) in CSR order

// per-layer raw BN stats: layer l -> [sum1:256 | sq1:256 | sum2:128 | sq2:128]
#define STATS_STRIDE 768
__device__ float g_stats[MAXL * STATS_STRIDE];

__device__ float g_rep [MAXG * DIM];
__device__ float g_fca [MAXG * 1024];
__device__ float g_fcb [MAXG * 1024];
__device__ float g_fcc [MAXG * 512];

// ---------------------------------------------------------------------------
// tf32 helpers
// ---------------------------------------------------------------------------
__device__ __forceinline__ uint32_t f2tf32(float x)
{
    uint32_t r;
    asm volatile("cvt.rna.tf32.f32 %0, %1;" : "=r"(r) : "f"(x));
    return r;
}

__device__ __forceinline__ void split_tf32(float v, float& big, float& small)
{
    uint32_t bu = f2tf32(v);
    float bf = __uint_as_float(bu);
    big = bf;
    small = __uint_as_float(f2tf32(v - bf));
}

__device__ __forceinline__ void mma8(float* d, const uint32_t* a, const uint32_t* b)
{
    asm volatile(
        "mma.sync.aligned.m16n8k8.row.col.f32.tf32.tf32.f32 "
        "{%0,%1,%2,%3}, {%4,%5,%6,%7}, {%8,%9}, {%0,%1,%2,%3};\n"
        : "+f"(d[0]), "+f"(d[1]), "+f"(d[2]), "+f"(d[3])
        : "r"(a[0]), "r"(a[1]), "r"(a[2]), "r"(a[3]), "r"(b[0]), "r"(b[1]));
}

// ---------------------------------------------------------------------------
// CSR construction (edge topology is layer-invariant)
// ---------------------------------------------------------------------------
__global__ void count_deg_kernel(const int* __restrict__ ei, int* __restrict__ cnt, int E)
{
    int e = blockIdx.x * blockDim.x + threadIdx.x;
    if (e >= E) return;
    atomicAdd(&cnt[__ldg(&ei[E + e])], 1);
}

// strip-per-thread exclusive scan, single block of 1024 threads
__global__ void scan_kernel(const int* __restrict__ cnt, int* __restrict__ rowptr, int N)
{
    __shared__ int tot[1024];
    int tid = threadIdx.x;
    int stride = (N + 1023) / 1024;
    int i0 = tid * stride;
    int i1 = min(i0 + stride, N);
    if (i0 > N) i0 = N;

    int s = 0;
    for (int i = i0; i < i1; i++) s += cnt[i];
    tot[tid] = s;
    __syncthreads();

    #pragma unroll
    for (int off = 1; off < 1024; off <<= 1) {
        int v = (tid >= off) ? tot[tid - off] : 0;
        __syncthreads();
        tot[tid] += v;
        __syncthreads();
    }

    int run = (tid > 0) ? tot[tid - 1] : 0;
    for (int i = i0; i < i1; i++) { rowptr[i] = run; run += cnt[i]; }
    if (tid == 1023) rowptr[N] = tot[1023];
}

__global__ void scatter_csr_kernel(const int* __restrict__ ei,
                                   const int* __restrict__ attr,
                                   const int* __restrict__ rowptr,
                                   int* __restrict__ cnt,
                                   int4* __restrict__ csr, int E)
{
    int e = blockIdx.x * blockDim.x + threadIdx.x;
    if (e >= E) return;
    int dst = __ldg(&ei[E + e]);
    int pos = atomicAdd(&cnt[dst], 1);
    csr[__ldg(&rowptr[dst]) + pos] =
        make_int4(__ldg(&ei[e]), __ldg(&attr[e * 3 + 0]),
                  __ldg(&attr[e * 3 + 1]), __ldg(&attr[e * 3 + 2]));
}

// ---------------------------------------------------------------------------
// Atom encoder
// ---------------------------------------------------------------------------
__global__ void atom_encode_kernel(const int* __restrict__ x,
                                   const float* __restrict__ emb,
                                   float* __restrict__ h,
                                   float* __restrict__ hsum,
                                   int N)
{
    int gid  = blockIdx.x * blockDim.x + threadIdx.x;
    int node = gid >> 5;
    int lane = gid & 31;
    if (node >= N) return;

    float4 acc = make_float4(0.f, 0.f, 0.f, 0.f);
    #pragma unroll
    for (int f = 0; f < 9; f++) {
        int a = __ldg(&x[node * 9 + f]);
        const float4* p = reinterpret_cast<const float4*>(emb) + (size_t)(f * VV + a) * (DIM / 4);
        float4 v = __ldg(&p[lane]);
        acc.x += v.x; acc.y += v.y; acc.z += v.z; acc.w += v.w;
    }
    size_t o = (size_t)node * (DIM / 4) + lane;
    reinterpret_cast<float4*>(h)[o]    = acc;
    reinterpret_cast<float4*>(hsum)[o] = acc;
}

// ---------------------------------------------------------------------------
// Gather aggregation (packed CSR, GIN combine folded in):
// agg[n] = (1+eps)*h[n] + sum_{e: dst==n} relu(h[src] + e0 + e1 + e2)
// One warp per node, lane owns one float4. 2-way unrolled edge loop for MLP.
// ---------------------------------------------------------------------------
__global__ void agg_gather_kernel(const float* __restrict__ h,
                                  float* __restrict__ agg,
                                  const int* __restrict__ rowptr,
                                  const int4* __restrict__ csr,
                                  const float* __restrict__ bond,  // + l*3*VV*DIM
                                  const float* __restrict__ epsP, int lidx,
                                  int N)
{
    int gid  = blockIdx.x * blockDim.x + threadIdx.x;
    int node = gid >> 5;
    int lane = gid & 31;
    if (node >= N) return;

    int j0 = __ldg(&rowptr[node]);
    int j1 = __ldg(&rowptr[node + 1]);

    const float4* h4 = reinterpret_cast<const float4*>(h);
    const float4* b4 = reinterpret_cast<const float4*>(bond);

    const float ce = 1.0f + __ldg(&epsP[lidx]);
    float4 hv = __ldg(&h4[(size_t)node * (DIM / 4) + lane]);
    float4 acc = make_float4(ce * hv.x, ce * hv.y, ce * hv.z, ce * hv.w);

    int j = j0;
    for (; j + 2 <= j1; j += 2) {
        int4 c0 = __ldg(&csr[j]);
        int4 c1 = __ldg(&csr[j + 1]);

        float4 v0  = __ldg(&h4[(size_t)c0.x * (DIM / 4) + lane]);
        float4 v1  = __ldg(&h4[(size_t)c1.x * (DIM / 4) + lane]);
        float4 ea0 = __ldg(&b4[(0 * VV + c0.y) * (DIM / 4) + lane]);
        float4 ea1 = __ldg(&b4[(0 * VV + c1.y) * (DIM / 4) + lane]);
        float4 eb0 = __ldg(&b4[(1 * VV + c0.z) * (DIM / 4) + lane]);
        float4 eb1 = __ldg(&b4[(1 * VV + c1.z) * (DIM / 4) + lane]);
        float4 ec0 = __ldg(&b4[(2 * VV + c0.w) * (DIM / 4) + lane]);
        float4 ec1 = __ldg(&b4[(2 * VV + c1.w) * (DIM / 4) + lane]);

        acc.x += fmaxf(v0.x + ea0.x + eb0.x + ec0.x, 0.f)
               + fmaxf(v1.x + ea1.x + eb1.x + ec1.x, 0.f);
        acc.y += fmaxf(v0.y + ea0.y + eb0.y + ec0.y, 0.f)
               + fmaxf(v1.y + ea1.y + eb1.y + ec1.y, 0.f);
        acc.z += fmaxf(v0.z + ea0.z + eb0.z + ec0.z, 0.f)
               + fmaxf(v1.z + ea1.z + eb1.z + ec1.z, 0.f);
        acc.w += fmaxf(v0.w + ea0.w + eb0.w + ec0.w, 0.f)
               + fmaxf(v1.w + ea1.w + eb1.w + ec1.w, 0.f);
    }
    if (j < j1) {
        int4 c = __ldg(&csr[j]);
        float4 v  = __ldg(&h4[(size_t)c.x * (DIM / 4) + lane]);
        float4 e0 = __ldg(&b4[(0 * VV + c.y) * (DIM / 4) + lane]);
        float4 e1 = __ldg(&b4[(1 * VV + c.z) * (DIM / 4) + lane]);
        float4 e2 = __ldg(&b4[(2 * VV + c.w) * (DIM / 4) + lane]);
        acc.x += fmaxf(v.x + e0.x + e1.x + e2.x, 0.f);
        acc.y += fmaxf(v.y + e0.y + e1.y + e2.y, 0.f);
        acc.z += fmaxf(v.z + e0.z + e1.z + e2.z, 0.f);
        acc.w += fmaxf(v.w + e0.w + e1.w + e2.w, 0.f);
    }
    reinterpret_cast<float4*>(agg)[(size_t)node * (DIM / 4) + lane] = acc;
}

// ---------------------------------------------------------------------------
// Tensor-core GEMM (3xTF32), 256 threads (8 warps, warp tile 64x32),
// double-buffered smem, 1 sync/stage.
//   AMODE 0: A as-is
//   AMODE 2: A' = relu(bn(A)) with scale/shift computed in-kernel from stats
// Optional fused epilogue: relu, column sum/sum-sq into csum/csq.
// Block tile 128x128, BK=32, mma.m16n8k8.tf32, XOR swizzle.
// Dynamic smem: 2 x 16384 floats + 512 floats = 133120 bytes.
// Requires N%128==0, K%32==0.
// ---------------------------------------------------------------------------
template <int AMODE, bool RELU_OUT, bool STATS>
__global__ __launch_bounds__(256)
void mma_gemm_kernel(const float* __restrict__ A,
                     const float* __restrict__ B,
                     const float* __restrict__ bias,
                     const float* __restrict__ bnsum,
                     const float* __restrict__ bnsq,
                     const float* __restrict__ bng,
                     const float* __restrict__ bnb,
                     float invN,
                     float* __restrict__ C,
                     int M, int N, int K,
                     float* __restrict__ csum,
                     float* __restrict__ csq)
{
    extern __shared__ float smbase[];
    float* sS = smbase + 32768;   // [K<=256] BN scale
    float* sT = smbase + 33024;   // [K<=256] BN shift

    const int tid = threadIdx.x;
    const int bm = blockIdx.y * 128;
    const int bn = blockIdx.x * 128;

    if (AMODE == 2) {
        for (int c = tid; c < K; c += 256) {
            float mu  = __ldg(&bnsum[c]) * invN;
            float var = __ldg(&bnsq[c]) * invN - mu * mu;
            float s   = rsqrtf(var + 1e-5f) * __ldg(&bng[c]);
            sS[c] = s;
            sT[c] = __ldg(&bnb[c]) - mu * s;
        }
        __syncthreads();
    }

    const int q  = tid & 7;          // A k-quad (0..7)
    const int r0 = tid >> 3;         // A row base (0..31)
    const int kb = tid >> 5;         // B k base (0..7)
    const int n4 = (tid & 31) * 4;   // B col

    float4 ra[4], rb[4];

    auto load_stage = [&](int k0) {
        #pragma unroll
        for (int i = 0; i < 4; i++) {
            int grow = bm + r0 + 32 * i;
            ra[i] = (grow < M)
                ? *reinterpret_cast<const float4*>(A + (size_t)grow * K + k0 + q * 4)
                : make_float4(0.f, 0.f, 0.f, 0.f);
        }
        #pragma unroll
        for (int i = 0; i < 4; i++) {
            int k = kb + 8 * i;
            rb[i] = *reinterpret_cast<const float4*>(B + (size_t)(k0 + k) * N + bn + n4);
        }
    };

    auto store_stage = [&](int k0, float* buf) {
        float* sAb = buf;
        float* sAs = buf + 4096;
        float* sBb = buf + 8192;
        float* sBs = buf + 12288;
        #pragma unroll
        for (int i = 0; i < 4; i++) {
            int r = r0 + 32 * i;
            float4 v = ra[i];
            if (AMODE == 2) {
                int kk = k0 + q * 4;
                v.x = fmaxf(v.x * sS[kk + 0] + sT[kk + 0], 0.f);
                v.y = fmaxf(v.y * sS[kk + 1] + sT[kk + 1], 0.f);
                v.z = fmaxf(v.z * sS[kk + 2] + sT[kk + 2], 0.f);
                v.w = fmaxf(v.w * sS[kk + 3] + sT[kk + 3], 0.f);
            }
            float4 bg, sl;
            split_tf32(v.x, bg.x, sl.x);
            split_tf32(v.y, bg.y, sl.y);
            split_tf32(v.z, bg.z, sl.z);
            split_tf32(v.w, bg.w, sl.w);
            int addr = r * 32 + ((q * 4) ^ ((r & 7) * 4));
            *reinterpret_cast<float4*>(sAb + addr) = bg;
            *reinterpret_cast<float4*>(sAs + addr) = sl;
        }
        #pragma unroll
        for (int i = 0; i < 4; i++) {
            int k = kb + 8 * i;
            float4 v = rb[i];
            float4 bg, sl;
            split_tf32(v.x, bg.x, sl.x);
            split_tf32(v.y, bg.y, sl.y);
            split_tf32(v.z, bg.z, sl.z);
            split_tf32(v.w, bg.w, sl.w);
            int addr = k * 128 + (n4 ^ ((k & 3) * 8));
            *reinterpret_cast<float4*>(sBb + addr) = bg;
            *reinterpret_cast<float4*>(sBs + addr) = sl;
        }
    };

    const int lane = tid & 31;
    const int warp = tid >> 5;
    const int wm = warp & 1;
    const int wn = warp >> 1;
    const int grp = lane >> 2;
    const int tig = lane & 3;
    const int swA = grp * 4;
    const int swB = tig * 8;

    float acc[4][4][4];
    #pragma unroll
    for (int mt = 0; mt < 4; mt++)
        #pragma unroll
        for (int nt = 0; nt < 4; nt++)
            #pragma unroll
            for (int i = 0; i < 4; i++) acc[mt][nt][i] = 0.f;

    auto compute_stage = [&](const float* buf) {
        const uint32_t* uAb = reinterpret_cast<const uint32_t*>(buf);
        const uint32_t* uAs = uAb + 4096;
        const uint32_t* uBb = uAb + 8192;
        const uint32_t* uBs = uAb + 12288;
        #pragma unroll
        for (int kk = 0; kk < 4; kk++) {
            int kk8 = kk * 8 + tig;
            int c0 = kk8 ^ swA;
            int c1 = c0 ^ 4;
            uint32_t ab[4][4], as_[4][4], bbf[4][2], bsf[4][2];
            #pragma unroll
            for (int mt = 0; mt < 4; mt++) {
                int m = wm * 64 + mt * 16 + grp;
                ab[mt][0]  = uAb[m * 32 + c0];
                ab[mt][1]  = uAb[(m + 8) * 32 + c0];
                ab[mt][2]  = uAb[m * 32 + c1];
                ab[mt][3]  = uAb[(m + 8) * 32 + c1];
                as_[mt][0] = uAs[m * 32 + c0];
                as_[mt][1] = uAs[(m + 8) * 32 + c0];
                as_[mt][2] = uAs[m * 32 + c1];
                as_[mt][3] = uAs[(m + 8) * 32 + c1];
            }
            #pragma unroll
            for (int nt = 0; nt < 4; nt++) {
                int n = wn * 32 + nt * 8 + grp;
                int a0 = kk8 * 128 + (n ^ swB);
                bbf[nt][0] = uBb[a0];
                bbf[nt][1] = uBb[a0 + 512];
                bsf[nt][0] = uBs[a0];
                bsf[nt][1] = uBs[a0 + 512];
            }
            #pragma unroll
            for (int mt = 0; mt < 4; mt++)
                #pragma unroll
                for (int nt = 0; nt < 4; nt++) {
                    mma8(acc[mt][nt], ab[mt],  bbf[nt]);
                    mma8(acc[mt][nt], as_[mt], bbf[nt]);
                    mma8(acc[mt][nt], ab[mt],  bsf[nt]);
                }
        }
    };

    // ---- double-buffered main loop: one sync per stage ----
    const int nst = K >> 5;
    load_stage(0);
    store_stage(0, smbase);
    __syncthreads();
    for (int s = 0; s < nst; s++) {
        if (s + 1 < nst) {
            load_stage((s + 1) << 5);
            store_stage((s + 1) << 5, smbase + ((s + 1) & 1) * 16384);
        }
        compute_stage(smbase + (s & 1) * 16384);
        __syncthreads();
    }

    // ---- epilogue: bias, opt relu, store, fused column stats ----
    float* ssum = smbase;
    float* ssq  = smbase + 128;
    if (STATS) {
        smbase[tid] = 0.f;
        __syncthreads();
    }

    float ps[4][2] = {}, pq[4][2] = {};
    #pragma unroll
    for (int mt = 0; mt < 4; mt++) {
        #pragma unroll
        for (int half = 0; half < 2; half++) {
            int row = bm + wm * 64 + mt * 16 + half * 8 + grp;
            bool ok = (row < M);
            #pragma unroll
            for (int nt = 0; nt < 4; nt++) {
                int coll = wn * 32 + nt * 8 + tig * 2;
                float v0 = acc[mt][nt][half * 2 + 0] + __ldg(&bias[bn + coll]);
                float v1 = acc[mt][nt][half * 2 + 1] + __ldg(&bias[bn + coll + 1]);
                if (RELU_OUT) { v0 = fmaxf(v0, 0.f); v1 = fmaxf(v1, 0.f); }
                if (ok) {
                    *reinterpret_cast<float2*>(C + (size_t)row * N + bn + coll) =
                        make_float2(v0, v1);
                    if (STATS) {
                        ps[nt][0] += v0; pq[nt][0] += v0 * v0;
                        ps[nt][1] += v1; pq[nt][1] += v1 * v1;
                    }
                }
            }
        }
    }
    if (STATS) {
        #pragma unroll
        for (int nt = 0; nt < 4; nt++) {
            int coll = wn * 32 + nt * 8 + tig * 2;
            atomicAdd(&ssum[coll],     ps[nt][0]);
            atomicAdd(&ssum[coll + 1], ps[nt][1]);
            atomicAdd(&ssq[coll],      pq[nt][0]);
            atomicAdd(&ssq[coll + 1],  pq[nt][1]);
        }
        __syncthreads();
        if (tid < 128) {
            atomicAdd(&csum[bn + tid], ssum[tid]);
            atomicAdd(&csq [bn + tid], ssq[tid]);
        }
    }
}

// ---------------------------------------------------------------------------
// Node update: h = bn(h_pre) [opt relu]; h_sum += h (BN params in-kernel)
// ---------------------------------------------------------------------------
__global__ void node_update_kernel(const float* __restrict__ hpre,
                                   const float* __restrict__ bnsum,
                                   const float* __restrict__ bnsq,
                                   const float* __restrict__ gamma,
                                   const float* __restrict__ beta,
                                   float invN,
                                   float* __restrict__ h,
                                   float* __restrict__ hsum,
                                   int N, int do_relu)
{
    __shared__ float sS[DIM], sT[DIM];
    if (threadIdx.x < DIM) {
        int c = threadIdx.x;
        float mu  = __ldg(&bnsum[c]) * invN;
        float var = __ldg(&bnsq[c]) * invN - mu * mu;
        float s   = rsqrtf(var + 1e-5f) * __ldg(&gamma[c]);
        sS[c] = s;
        sT[c] = __ldg(&beta[c]) - mu * s;
    }
    __syncthreads();

    int idx = blockIdx.x * blockDim.x + threadIdx.x;
    int total = N * (DIM / 4);
    if (idx >= total) return;
    int c4 = (idx & (DIM / 4 - 1)) * 4;

    float4 v = reinterpret_cast<const float4*>(hpre)[idx];
    v.x = v.x * sS[c4 + 0] + sT[c4 + 0];
    v.y = v.y * sS[c4 + 1] + sT[c4 + 1];
    v.z = v.z * sS[c4 + 2] + sT[c4 + 2];
    v.w = v.w * sS[c4 + 3] + sT[c4 + 3];
    if (do_relu) {
        v.x = fmaxf(v.x, 0.f); v.y = fmaxf(v.y, 0.f);
        v.z = fmaxf(v.z, 0.f); v.w = fmaxf(v.w, 0.f);
    }
    reinterpret_cast<float4*>(h)[idx] = v;
    float4 hs = reinterpret_cast<float4*>(hsum)[idx];
    hs.x += v.x; hs.y += v.y; hs.z += v.z; hs.w += v.w;
    reinterpret_cast<float4*>(hsum)[idx] = hs;
}

// ---------------------------------------------------------------------------
// Global mean pool
// ---------------------------------------------------------------------------
__device__ __forceinline__ int lower_bound_dev(const int* a, int n, int val)
{
    int lo = 0, hi = n;
    while (lo < hi) {
        int mid = (lo + hi) >> 1;
        if (a[mid] < val) lo = mid + 1; else hi = mid;
    }
    return lo;
}

__global__ void pool_kernel(const float* __restrict__ hsum,
                            const int* __restrict__ batch,
                            float* __restrict__ rep,
                            int N)
{
    int g = blockIdx.x;
    int s = lower_bound_dev(batch, N, g);
    int e = lower_bound_dev(batch, N, g + 1);
    float acc = 0.f;
    for (int n = s; n < e; n++)
        acc += hsum[(size_t)n * DIM + threadIdx.x];
    float cnt = (float)(e - s);
    rep[(size_t)g * DIM + threadIdx.x] = acc / fmaxf(cnt, 1.0f);
}

// ---------------------------------------------------------------------------
// Final FC4
// ---------------------------------------------------------------------------
__global__ void fc4_kernel(const float* __restrict__ zc,
                           const float* __restrict__ w,
                           const float* __restrict__ b,
                           float* __restrict__ out,
                           int G)
{
    int gid  = blockIdx.x * blockDim.x + threadIdx.x;
    int g    = gid >> 5;
    int lane = gid & 31;
    if (g >= G) return;
    float acc = 0.f;
    #pragma unroll 4
    for (int k = lane; k < 512; k += 32)
        acc = fmaf(zc[(size_t)g * 512 + k], __ldg(&w[k]), acc);
    #pragma unroll
    for (int off = 16; off > 0; off >>= 1)
        acc += __shfl_xor_sync(0xffffffffu, acc, off);
    if (lane == 0) out[g] = acc + __ldg(&b[0]);
}

// ---------------------------------------------------------------------------
// Launch
// ---------------------------------------------------------------------------
extern "C" void kernel_launch(void* const* d_in, const int* in_sizes, int n_in,
                              void* d_out, int out_size)
{
    const int*   x        = (const int*)  d_in[0];
    const int*   ei       = (const int*)  d_in[1];
    const int*   attr     = (const int*)  d_in[2];
    const int*   batch    = (const int*)  d_in[3];
    const float* atom_emb = (const float*)d_in[4];
    const float* bond_emb = (const float*)d_in[5];
    const float* eps      = (const float*)d_in[6];
    const float* W1   = (const float*)d_in[7];
    const float* b1   = (const float*)d_in[8];
    const float* g1   = (const float*)d_in[9];
    const float* be1  = (const float*)d_in[10];
    const float* W2   = (const float*)d_in[11];
    const float* b2   = (const float*)d_in[12];
    const float* bn_g = (const float*)d_in[13];
    const float* bn_b = (const float*)d_in[14];
    const float* fcW1 = (const float*)d_in[15];
    const float* fcb1 = (const float*)d_in[16];
    const float* fcW2 = (const float*)d_in[17];
    const float* fcb2 = (const float*)d_in[18];
    const float* fcW3 = (const float*)d_in[19];
    const float* fcb3 = (const float*)d_in[20];
    const float* fcW4 = (const float*)d_in[21];
    const float* fcb4 = (const float*)d_in[22];
    float* out = (float*)d_out;

    const int N = in_sizes[0] / 9;
    const int E = in_sizes[1] / 2;
    const int G = out_size;
    const int L = in_sizes[6];

    float *h, *hsum, *agg, *z1, *hpre, *stats;
    float *rep, *fca, *fcb, *fcc;
    int *rowptr, *cnt;
    int4 *csr;
    cudaGetSymbolAddress((void**)&h,    g_h);
    cudaGetSymbolAddress((void**)&hsum, g_hsum);
    cudaGetSymbolAddress((void**)&agg,  g_agg);
    cudaGetSymbolAddress((void**)&z1,   g_z1);
    cudaGetSymbolAddress((void**)&hpre, g_hpre);
    cudaGetSymbolAddress((void**)&stats, g_stats);
    cudaGetSymbolAddress((void**)&rep,  g_rep);
    cudaGetSymbolAddress((void**)&fca,  g_fca);
    cudaGetSymbolAddress((void**)&fcb,  g_fcb);
    cudaGetSymbolAddress((void**)&fcc,  g_fcc);
    cudaGetSymbolAddress((void**)&rowptr, g_rowptr);
    cudaGetSymbolAddress((void**)&cnt,    g_cnt);
    cudaGetSymbolAddress((void**)&csr,    g_csr);

    const float invN = 1.0f / (float)N;
    const int SMEM_MMA = 133120;   // 2*16384 + 512 floats

    cudaFuncSetAttribute(mma_gemm_kernel<0, false, true>,
                         cudaFuncAttributeMaxDynamicSharedMemorySize, SMEM_MMA);
    cudaFuncSetAttribute(mma_gemm_kernel<2, false, true>,
                         cudaFuncAttributeMaxDynamicSharedMemorySize, SMEM_MMA);
    cudaFuncSetAttribute(mma_gemm_kernel<0, true, false>,
                         cudaFuncAttributeMaxDynamicSharedMemorySize, SMEM_MMA);

    // ---- upfront zeroing of all per-layer stat slices (one memset) ----
    cudaMemsetAsync(stats, 0, (size_t)L * STATS_STRIDE * sizeof(float));

    // ---- CSR build ----
    cudaMemsetAsync(cnt, 0, N * sizeof(int));
    count_deg_kernel<<<(E + 255) / 256, 256>>>(ei, cnt, E);
    scan_kernel<<<1, 1024>>>(cnt, rowptr, N);
    cudaMemsetAsync(cnt, 0, N * sizeof(int));
    scatter_csr_kernel<<<(E + 255) / 256, 256>>>(ei, attr, rowptr, cnt, csr, E);

    // AtomEncoder + h_sum init
    atom_encode_kernel<<<(N + 7) / 8, 256>>>(x, atom_emb, h, hsum, N);

    const int mblocks = (N + 127) / 128;

    for (int l = 0; l < L; l++) {
        float* sum1 = stats + (size_t)l * STATS_STRIDE;
        float* sq1  = sum1 + 256;
        float* sum2 = sum1 + 512;
        float* sq2  = sum1 + 640;

        // message + aggregate + GIN combine (gather, packed CSR, no atomics)
        agg_gather_kernel<<<(N * 32 + 255) / 256, 256>>>(
            h, agg, rowptr, csr, bond_emb + (size_t)l * 3 * VV * DIM,
            eps, l, N);

        // z1 = agg @ W1 + b1  (stats fused into epilogue)
        mma_gemm_kernel<0, false, true><<<dim3(HID / 128, mblocks), 256, SMEM_MMA>>>(
            agg, W1, b1, nullptr, nullptr, nullptr, nullptr, invN,
            z1, N, HID, DIM, sum1, sq1);

        // h_pre = relu(bn(z1)) @ W2 + b2  (BN params computed in-kernel)
        mma_gemm_kernel<2, false, true><<<dim3(DIM / 128, mblocks), 256, SMEM_MMA>>>(
            z1, W2, b2, sum1, sq1, g1, be1, invN,
            hpre, N, DIM, HID, sum2, sq2);

        // h = bn(h_pre) [relu if not last]; h_sum += h  (BN params in-kernel)
        node_update_kernel<<<(N * (DIM / 4) + 255) / 256, 256>>>(
            hpre, sum2, sq2, bn_g + (size_t)l * DIM, bn_b + (size_t)l * DIM,
            invN, h, hsum, N, (l < L - 1) ? 1 : 0);
    }

    // global mean pool
    pool_kernel<<<G, DIM>>>(hsum, batch, rep, N);

    // FC head (tensor cores)
    const int gblocks = (G + 127) / 128;
    mma_gemm_kernel<0, true, false><<<dim3(1024 / 128, gblocks), 256, SMEM_MMA>>>(
        rep, fcW1, fcb1, nullptr, nullptr, nullptr, nullptr, invN,
        fca, G, 1024, DIM, nullptr, nullptr);
    mma_gemm_kernel<0, true, false><<<dim3(1024 / 128, gblocks), 256, SMEM_MMA>>>(
        fca, fcW2, fcb2, nullptr, nullptr, nullptr, nullptr, invN,
        fcb, G, 1024, 1024, nullptr, nullptr);
    mma_gemm_kernel<0, true, false><<<dim3(512 / 128, gblocks), 256, SMEM_MMA>>>(
        fcb, fcW3, fcb3, nullptr, nullptr, nullptr, nullptr, invN,
        fcc, G, 512, 1024, nullptr, nullptr);
    fc4_kernel<<<(G + 7) / 8, 256>>>(fcc, fcW4, fcb4, out, G);
}